// round 2
// baseline (speedup 1.0000x reference)
#include <cuda_runtime.h>
#include <cstdint>
#include <cstddef>

// Problem constants
#define NN    1024
#define FIN   64
#define FHID  128
#define FOUT  64
#define TM    128
#define TK    32
#define NTHREADS 256

// Shared memory layout (float offsets).
// Strides chosen for conflict-free mma fragment loads:
//   A-operand layouts ([m][k]): stride % 32 == 4  -> 36, 68, 132
//   B-operand layouts ([k][n]): stride % 32 == 8  -> 72, 136, 72
#define AS_FLOATS (128*36)
#define BS_FLOATS (32*72)
#define AS_BASE 0
#define BS_BASE (3*AS_FLOATS)                 // 13824
#define W1_BASE (BS_BASE + 3*BS_FLOATS)       // 20736
#define W2_BASE (W1_BASE + 64*136)            // 29440
#define B1_BASE (W2_BASE + 128*72)            // 38656
#define B2_BASE (B1_BASE + 128)               // 38784
#define G_BASE  (B2_BASE + 64)                // 38848
#define HS_BASE 0                              // overlays As (dead after mainloop)
#define SMEM_FLOATS (G_BASE + 128*132)        // 55744 floats = 222976 bytes

// Mask dtype mode, set by probe kernel each launch: 0=int32, 1=uint8/bool, 2=float32
__device__ int g_mask_mode;

__global__ void probe_mask_kernel(const unsigned char* __restrict__ m) {
    __shared__ int s_gt1, s_nzoff;
    if (threadIdx.x == 0) { s_gt1 = 0; s_nzoff = 0; }
    __syncthreads();
    int gt1 = 0, nzoff = 0;
    // 65536 bytes scanned by 256 threads, 16B vector loads
    const uint4* v = (const uint4*)m;
    for (int i = threadIdx.x; i < 4096; i += 256) {
        uint4 u = v[i];
        unsigned words[4] = {u.x, u.y, u.z, u.w};
        #pragma unroll
        for (int wi = 0; wi < 4; ++wi) {
            unsigned wv = words[wi];
            #pragma unroll
            for (int bi = 0; bi < 4; ++bi) {
                unsigned byte = (wv >> (bi * 8)) & 0xFF;
                if (byte > 1) gt1 = 1;
                if (byte != 0 && ((wi * 4 + bi) & 3) != 0) nzoff = 1;
            }
        }
    }
    if (gt1) atomicOr(&s_gt1, 1);
    if (nzoff) atomicOr(&s_nzoff, 1);
    __syncthreads();
    if (threadIdx.x == 0) {
        int mode;
        if (s_gt1) mode = 2;            // float32 (bytes like 0x80/0x3F present)
        else if (s_nzoff) mode = 1;     // packed bytes (bool/uint8)
        else mode = 0;                  // int32 (payload byte every 4th position)
        g_mask_mode = mode;
    }
}

__device__ __forceinline__ unsigned f2tf(float f) {
    unsigned u;
    asm("cvt.rna.tf32.f32 %0, %1;" : "=r"(u) : "f"(f));
    return u;
}

__device__ __forceinline__ void mma8(float* c, const unsigned* a, const unsigned* b) {
    asm volatile(
        "mma.sync.aligned.m16n8k8.row.col.f32.tf32.tf32.f32 "
        "{%0,%1,%2,%3},{%4,%5,%6,%7},{%8,%9},{%0,%1,%2,%3};"
        : "+f"(c[0]), "+f"(c[1]), "+f"(c[2]), "+f"(c[3])
        : "r"(a[0]), "r"(a[1]), "r"(a[2]), "r"(a[3]), "r"(b[0]), "r"(b[1]));
}

__device__ __forceinline__ void cp16(float* d, const float* s) {
    unsigned ds = (unsigned)__cvta_generic_to_shared(d);
    asm volatile("cp.async.cg.shared.global [%0], [%1], 16;" :: "r"(ds), "l"(s));
}
__device__ __forceinline__ void cpcommit() { asm volatile("cp.async.commit_group;"); }
template <int N> __device__ __forceinline__ void cpwait() {
    asm volatile("cp.async.wait_group %0;" :: "n"(N));
}

extern __shared__ float sm[];

__global__ void __launch_bounds__(NTHREADS, 1) gin_fused_kernel(
    const float* __restrict__ x, const float* __restrict__ adj,
    const unsigned char* __restrict__ mask,
    const float* __restrict__ W1, const float* __restrict__ b1,
    const float* __restrict__ W2, const float* __restrict__ b2,
    const float* __restrict__ eps, float* __restrict__ out)
{
    const int tid  = threadIdx.x;
    const int b    = blockIdx.x >> 3;
    const int m0   = (blockIdx.x & 7) * TM;
    const int lane = tid & 31;
    const int w    = tid >> 5;
    const int wm   = w >> 1;   // 0..3 (M direction)
    const int wn   = w & 1;    // 0..1 (N direction)
    const int lq   = lane >> 2;  // lane/4
    const int lr   = lane & 3;   // lane%4

    const float* adjbase = adj + ((size_t)b * NN + m0) * NN;
    const float* xb      = x + (size_t)b * NN * FIN;

    // ---------- prologue: weights + biases (group W) ----------
    #pragma unroll
    for (int t = 0; t < 8; ++t) {                  // W1: 64x128 -> padded 64x136
        int c = tid + t * NTHREADS;                // 2048 16B chunks
        int r = c >> 5, cc = c & 31;
        cp16(sm + W1_BASE + r * 136 + cc * 4, W1 + r * 128 + cc * 4);
    }
    #pragma unroll
    for (int t = 0; t < 8; ++t) {                  // W2: 128x64 -> padded 128x72
        int c = tid + t * NTHREADS;
        int r = c >> 4, cc = c & 15;
        cp16(sm + W2_BASE + r * 72 + cc * 4, W2 + r * 64 + cc * 4);
    }
    if (tid < 32) cp16(sm + B1_BASE + tid * 4, b1 + tid * 4);
    if (tid < 16) cp16(sm + B2_BASE + tid * 4, b2 + tid * 4);
    cpcommit();

    // ---------- tile loader (one commit group per tile) ----------
    auto load_tile = [&](int stage, int k0) {
        float* As = sm + AS_BASE + stage * AS_FLOATS;   // [128][36]  (m,k)
        float* Bs = sm + BS_BASE + stage * BS_FLOATS;   // [32][72]   (k,n)
        #pragma unroll
        for (int t = 0; t < 4; ++t) {                    // 1024 chunks of adj
            int c = tid + t * NTHREADS;
            int r = c >> 3, cc = c & 7;
            cp16(As + r * 36 + cc * 4, adjbase + (size_t)r * NN + k0 + cc * 4);
        }
        #pragma unroll
        for (int t = 0; t < 2; ++t) {                    // 512 chunks of x
            int c = tid + t * NTHREADS;
            int r = c >> 4, cc = c & 15;
            cp16(Bs + r * 72 + cc * 4, xb + (size_t)(k0 + r) * FIN + cc * 4);
        }
        cpcommit();
    };

    load_tile(0, 0);
    load_tile(1, TK);

    // ---------- GEMM1: agg = adj[b] @ x[b]  (M=128, N=64, K=1024) ----------
    float acc[2][4][4];
    #pragma unroll
    for (int i = 0; i < 2; ++i)
        #pragma unroll
        for (int j = 0; j < 4; ++j)
            #pragma unroll
            for (int k = 0; k < 4; ++k) acc[i][j][k] = 0.f;

    const int NITER = NN / TK;  // 32
    for (int it = 0; it < NITER; ++it) {
        if (it + 2 < NITER) load_tile((it + 2) % 3, (it + 2) * TK);
        if (it < NITER - 2)       cpwait<2>();
        else if (it == NITER - 2) cpwait<1>();
        else                      cpwait<0>();
        __syncthreads();

        const float* As = sm + AS_BASE + (it % 3) * AS_FLOATS;
        const float* Bs = sm + BS_BASE + (it % 3) * BS_FLOATS;
        #pragma unroll
        for (int ks = 0; ks < 4; ++ks) {
            int kk = ks * 8;
            unsigned a[2][4], bb[4][2];
            #pragma unroll
            for (int mf = 0; mf < 2; ++mf) {
                const float* ap = As + (wm * 32 + mf * 16 + lq) * 36 + kk + lr;
                a[mf][0] = f2tf(ap[0]);
                a[mf][1] = f2tf(ap[8 * 36]);
                a[mf][2] = f2tf(ap[4]);
                a[mf][3] = f2tf(ap[8 * 36 + 4]);
            }
            #pragma unroll
            for (int nf = 0; nf < 4; ++nf) {
                const float* bp = Bs + (kk + lr) * 72 + wn * 32 + nf * 8 + lq;
                bb[nf][0] = f2tf(bp[0]);
                bb[nf][1] = f2tf(bp[4 * 72]);
            }
            #pragma unroll
            for (int mf = 0; mf < 2; ++mf)
                #pragma unroll
                for (int nf = 0; nf < 4; ++nf)
                    mma8(acc[mf][nf], a[mf], bb[nf]);
        }
        __syncthreads();
    }

    // ---------- epilogue 1: Hs = agg, then Hs += (1+eps)*x ----------
    float* Hs = sm + HS_BASE;  // [128][68]
    #pragma unroll
    for (int mf = 0; mf < 2; ++mf) {
        int row = wm * 32 + mf * 16 + lq;
        #pragma unroll
        for (int nf = 0; nf < 4; ++nf) {
            int col = wn * 32 + nf * 8 + lr * 2;
            Hs[row * 68 + col]           = acc[mf][nf][0];
            Hs[row * 68 + col + 1]       = acc[mf][nf][1];
            Hs[(row + 8) * 68 + col]     = acc[mf][nf][2];
            Hs[(row + 8) * 68 + col + 1] = acc[mf][nf][3];
        }
    }
    __syncthreads();

    const float epsv = 1.0f + eps[0];
    #pragma unroll
    for (int t = 0; t < 32; ++t) {
        int idx = tid + t * NTHREADS;     // 8192 elements
        int r = idx >> 6, c = idx & 63;
        float xv = xb[(size_t)(m0 + r) * FIN + c];
        Hs[r * 68 + c] = fmaf(epsv, xv, Hs[r * 68 + c]);
    }
    __syncthreads();

    // ---------- GEMM2: G = relu(Hs @ W1 + b1)  (M=128, N=128, K=64) ----------
    float acc2[2][8][4];
    #pragma unroll
    for (int i = 0; i < 2; ++i)
        #pragma unroll
        for (int j = 0; j < 8; ++j)
            #pragma unroll
            for (int k = 0; k < 4; ++k) acc2[i][j][k] = 0.f;

    const float* W1s = sm + W1_BASE;  // [64][136]
    #pragma unroll
    for (int ks = 0; ks < 8; ++ks) {
        int kk = ks * 8;
        unsigned a[2][4], bb[8][2];
        #pragma unroll
        for (int mf = 0; mf < 2; ++mf) {
            const float* ap = Hs + (wm * 32 + mf * 16 + lq) * 68 + kk + lr;
            a[mf][0] = f2tf(ap[0]);
            a[mf][1] = f2tf(ap[8 * 68]);
            a[mf][2] = f2tf(ap[4]);
            a[mf][3] = f2tf(ap[8 * 68 + 4]);
        }
        #pragma unroll
        for (int nf = 0; nf < 8; ++nf) {
            const float* bp = W1s + (kk + lr) * 136 + wn * 64 + nf * 8 + lq;
            bb[nf][0] = f2tf(bp[0]);
            bb[nf][1] = f2tf(bp[4 * 136]);
        }
        #pragma unroll
        for (int mf = 0; mf < 2; ++mf)
            #pragma unroll
            for (int nf = 0; nf < 8; ++nf)
                mma8(acc2[mf][nf], a[mf], bb[nf]);
    }

    float* G = sm + G_BASE;             // [128][132]
    const float* b1s = sm + B1_BASE;
    #pragma unroll
    for (int mf = 0; mf < 2; ++mf) {
        int row = wm * 32 + mf * 16 + lq;
        #pragma unroll
        for (int nf = 0; nf < 8; ++nf) {
            int col = wn * 64 + nf * 8 + lr * 2;
            float bv0 = b1s[col], bv1 = b1s[col + 1];
            G[row * 132 + col]           = fmaxf(acc2[mf][nf][0] + bv0, 0.f);
            G[row * 132 + col + 1]       = fmaxf(acc2[mf][nf][1] + bv1, 0.f);
            G[(row + 8) * 132 + col]     = fmaxf(acc2[mf][nf][2] + bv0, 0.f);
            G[(row + 8) * 132 + col + 1] = fmaxf(acc2[mf][nf][3] + bv1, 0.f);
        }
    }
    __syncthreads();

    // ---------- GEMM3: out = G @ W2 + b2, masked  (M=128, N=64, K=128) ----------
    float acc3[2][4][4];
    #pragma unroll
    for (int i = 0; i < 2; ++i)
        #pragma unroll
        for (int j = 0; j < 4; ++j)
            #pragma unroll
            for (int k = 0; k < 4; ++k) acc3[i][j][k] = 0.f;

    const float* W2s = sm + W2_BASE;  // [128][72]
    #pragma unroll
    for (int ks = 0; ks < 16; ++ks) {
        int kk = ks * 8;
        unsigned a[2][4], bb[4][2];
        #pragma unroll
        for (int mf = 0; mf < 2; ++mf) {
            const float* ap = G + (wm * 32 + mf * 16 + lq) * 132 + kk + lr;
            a[mf][0] = f2tf(ap[0]);
            a[mf][1] = f2tf(ap[8 * 132]);
            a[mf][2] = f2tf(ap[4]);
            a[mf][3] = f2tf(ap[8 * 132 + 4]);
        }
        #pragma unroll
        for (int nf = 0; nf < 4; ++nf) {
            const float* bp = W2s + (kk + lr) * 72 + wn * 32 + nf * 8 + lq;
            bb[nf][0] = f2tf(bp[0]);
            bb[nf][1] = f2tf(bp[4 * 72]);
        }
        #pragma unroll
        for (int mf = 0; mf < 2; ++mf)
            #pragma unroll
            for (int nf = 0; nf < 4; ++nf)
                mma8(acc3[mf][nf], a[mf], bb[nf]);
    }

    // mask accessor: mode decided by probe kernel (same stream, already done)
    const int mmode = g_mask_mode;
    auto mask_at = [&](int idx) -> bool {
        if (mmode == 0) return ((const int*)mask)[idx] != 0;
        if (mmode == 2) return ((const float*)mask)[idx] != 0.0f;
        return mask[idx] != 0;
    };

    const float* b2s = sm + B2_BASE;
    #pragma unroll
    for (int mf = 0; mf < 2; ++mf) {
        int row  = wm * 32 + mf * 16 + lq;
        int grow = m0 + row;
        bool mk0 = mask_at(b * NN + grow);
        bool mk1 = mask_at(b * NN + grow + 8);
        #pragma unroll
        for (int nf = 0; nf < 4; ++nf) {
            int col = wn * 32 + nf * 8 + lr * 2;
            float bv0 = b2s[col], bv1 = b2s[col + 1];
            float o0 = acc3[mf][nf][0] + bv0;
            float o1 = acc3[mf][nf][1] + bv1;
            float o2 = acc3[mf][nf][2] + bv0;
            float o3 = acc3[mf][nf][3] + bv1;
            float* op0 = out + ((size_t)b * NN + grow) * FOUT + col;
            float* op1 = out + ((size_t)b * NN + grow + 8) * FOUT + col;
            op0[0] = mk0 ? o0 : 0.f;
            op0[1] = mk0 ? o1 : 0.f;
            op1[0] = mk1 ? o2 : 0.f;
            op1[1] = mk1 ? o3 : 0.f;
        }
    }
}

extern "C" void kernel_launch(void* const* d_in, const int* in_sizes, int n_in,
                              void* d_out, int out_size)
{
    // Identify inputs by element count (robust to metadata ordering).
    const float *x = 0, *adj = 0, *W1 = 0, *W2 = 0, *b1 = 0, *b2 = 0, *eps = 0;
    const unsigned char* mask = 0;
    for (int i = 0; i < n_in; ++i) {
        switch (in_sizes[i]) {
            case 64 * 1024 * 64:   x    = (const float*)d_in[i]; break;         // 4194304
            case 64 * 1024 * 1024: adj  = (const float*)d_in[i]; break;         // 67108864
            case 64 * 1024:        mask = (const unsigned char*)d_in[i]; break; // 65536
            case 64 * 128:         if (!W1) W1 = (const float*)d_in[i];          // 8192 (W1 first)
                                   else     W2 = (const float*)d_in[i]; break;
            case 128:              b1   = (const float*)d_in[i]; break;
            case 64:               b2   = (const float*)d_in[i]; break;
            case 1:                eps  = (const float*)d_in[i]; break;
            default: break;
        }
    }
    float* out = (float*)d_out;

    probe_mask_kernel<<<1, 256>>>(mask);

    cudaFuncSetAttribute(gin_fused_kernel,
                         cudaFuncAttributeMaxDynamicSharedMemorySize,
                         SMEM_FLOATS * (int)sizeof(float));
    gin_fused_kernel<<<512, NTHREADS, SMEM_FLOATS * sizeof(float)>>>(
        x, adj, mask, W1, b1, W2, b2, eps, out);
}